// round 7
// baseline (speedup 1.0000x reference)
#include <cuda_runtime.h>
#include <cuda_bf16.h>
#include <cstdint>

#define BB 128          // batch
#define TT 64           // time steps
#define EE 300          // embed dim
#define HH 2048         // hidden
#define G4 8192         // 4*H

// ---------------- scratch (device globals; no allocation allowed) ----------
__device__ float g_gx2[(size_t)TT * 128 * 128 * 64];     // [t][cb][b][gate*16+hc]
__device__ __nv_bfloat16 g_w_hi[(size_t)G4 * HH];        // W_hh split hi
__device__ __nv_bfloat16 g_w_lo[(size_t)G4 * HH];        // W_hh split lo
__device__ __nv_bfloat16 g_h_hi[BB * HH];                // hidden state hi
__device__ __nv_bfloat16 g_h_lo[BB * HH];                // hidden state lo
__device__ float g_c2[BB * HH];                          // cell state [cb][b][16]

// single dynamic smem symbol shared by all kernels
extern __shared__ __align__(1024) char dyn_smem[];

// ---------------- helpers --------------------------------------------------
__device__ __forceinline__ uint32_t smem_u32(const void* p) {
    return (uint32_t)__cvta_generic_to_shared(p);
}
__device__ __forceinline__ void cp16(uint32_t dst, const void* src) {
    asm volatile("cp.async.ca.shared.global [%0], [%1], 16;\n" ::"r"(dst), "l"(src));
}
__device__ __forceinline__ void cp16z(uint32_t dst, const void* src, int bytes) {
    asm volatile("cp.async.ca.shared.global [%0], [%1], 16, %2;\n" ::"r"(dst), "l"(src), "r"(bytes));
}
__device__ __forceinline__ void cp_commit() { asm volatile("cp.async.commit_group;\n"); }
template <int N> __device__ __forceinline__ void cp_wait() {
    asm volatile("cp.async.wait_group %0;\n" ::"n"(N));
}
__device__ __forceinline__ void mma_bf16(float c[4], const uint32_t a[4], uint32_t b0,
                                         uint32_t b1) {
    asm volatile(
        "mma.sync.aligned.m16n8k16.row.col.f32.bf16.bf16.f32 "
        "{%0,%1,%2,%3},{%4,%5,%6,%7},{%8,%9},{%0,%1,%2,%3};\n"
        : "+f"(c[0]), "+f"(c[1]), "+f"(c[2]), "+f"(c[3])
        : "r"(a[0]), "r"(a[1]), "r"(a[2]), "r"(a[3]), "r"(b0), "r"(b1));
}
__device__ __forceinline__ void ldsm4(uint32_t r[4], uint32_t addr) {
    asm volatile("ldmatrix.sync.aligned.m8n8.x4.shared.b16 {%0,%1,%2,%3}, [%4];"
                 : "=r"(r[0]), "=r"(r[1]), "=r"(r[2]), "=r"(r[3])
                 : "r"(addr));
}
__device__ __forceinline__ float sigmoidf_(float x) { return 1.0f / (1.0f + __expf(-x)); }

#define SMEM_SWZ128(x) ((x) ^ (((x) >> 3) & 0x70))

// ---------------- init / W split -------------------------------------------
__global__ void zero_kernel() {
    int i = blockIdx.x * blockDim.x + threadIdx.x;
    if (i < BB * HH) {
        g_h_hi[i] = __float2bfloat16(0.f);
        g_h_lo[i] = __float2bfloat16(0.f);
        g_c2[i] = 0.f;
    }
}

__global__ void wsplit_kernel(const float* __restrict__ w) {
    size_t i = ((size_t)blockIdx.x * blockDim.x + threadIdx.x) * 4;
    if (i < (size_t)G4 * HH) {
        float4 v = *reinterpret_cast<const float4*>(w + i);
        float vv[4] = {v.x, v.y, v.z, v.w};
#pragma unroll
        for (int k = 0; k < 4; k++) {
            __nv_bfloat16 hi = __float2bfloat16(vv[k]);
            g_w_hi[i + k] = hi;
            g_w_lo[i + k] = __float2bfloat16(vv[k] - __bfloat162float(hi));
        }
    }
}

// ---------------- kernel 1: embedding gather + input projection (tf32 SIMT) -
#define LDA 36
#define XP_STAGE_FLOATS ((128 + 64) * LDA)
#define XP_SMEM_BYTES (2 * XP_STAGE_FLOATS * 4)

__device__ __forceinline__ void compute_block_tf32(const float* __restrict__ As,
                                                   const float* __restrict__ Bs,
                                                   float acc[2][4][4], int wm, int wn, int g,
                                                   int tig) {
#pragma unroll
    for (int k8 = 0; k8 < 32; k8 += 8) {
        uint32_t a[2][4];
#pragma unroll
        for (int mt = 0; mt < 2; mt++) {
            int r = wm + mt * 16;
            a[mt][0] = __float_as_uint(As[(r + g) * LDA + k8 + tig]);
            a[mt][1] = __float_as_uint(As[(r + g + 8) * LDA + k8 + tig]);
            a[mt][2] = __float_as_uint(As[(r + g) * LDA + k8 + tig + 4]);
            a[mt][3] = __float_as_uint(As[(r + g + 8) * LDA + k8 + tig + 4]);
        }
        uint32_t b[4][2];
#pragma unroll
        for (int nt = 0; nt < 4; nt++) {
            int cc = wn + nt * 8 + g;
            b[nt][0] = __float_as_uint(Bs[cc * LDA + k8 + tig]);
            b[nt][1] = __float_as_uint(Bs[cc * LDA + k8 + tig + 4]);
        }
#pragma unroll
        for (int mt = 0; mt < 2; mt++)
#pragma unroll
            for (int nt = 0; nt < 4; nt++) {
                float* c = acc[mt][nt];
                asm volatile(
                    "mma.sync.aligned.m16n8k8.row.col.f32.tf32.tf32.f32 "
                    "{%0,%1,%2,%3},{%4,%5,%6,%7},{%8,%9},{%0,%1,%2,%3};\n"
                    : "+f"(c[0]), "+f"(c[1]), "+f"(c[2]), "+f"(c[3])
                    : "r"(a[mt][0]), "r"(a[mt][1]), "r"(a[mt][2]), "r"(a[mt][3]), "r"(b[nt][0]),
                      "r"(b[nt][1]));
            }
    }
}

__global__ void __launch_bounds__(256) xproj_kernel(const int* __restrict__ input,
                                                    const float* __restrict__ embed,
                                                    const float* __restrict__ w_ih,
                                                    const float* __restrict__ b_ih,
                                                    const float* __restrict__ b_hh) {
    float* smem = reinterpret_cast<float*>(dyn_smem);
    __shared__ int tok[128];

    const int tid = threadIdx.x;
    const int t = blockIdx.x;
    const int n0 = blockIdx.y * 64;

    if (tid < 128) tok[tid] = input[tid * TT + t];
    __syncthreads();

    const int wid = tid >> 5, lane = tid & 31;
    const int wm = (wid & 3) * 32, wn = (wid >> 2) * 32;
    const int g = lane >> 2, tig = lane & 3;

    auto load_tiles = [&](int kb, int s) {
        float* As = smem + s * XP_STAGE_FLOATS;
        float* Bs = As + 128 * LDA;
        int k0 = kb * 32;
#pragma unroll
        for (int i = 0; i < 4; i++) {
            int lin = tid + i * 256;
            int row = lin >> 3;
            int kk4 = (lin & 7) * 4;
            int k = k0 + kk4;
            int rem = EE - k;
            int bytes = rem >= 4 ? 16 : (rem > 0 ? rem * 4 : 0);
            const float* src = embed + (size_t)tok[row] * EE + (bytes ? k : 0);
            cp16z(smem_u32(&As[row * LDA + kk4]), src, bytes);
        }
#pragma unroll
        for (int i = 0; i < 2; i++) {
            int lin = tid + i * 256;
            int col = lin >> 3;
            int kk4 = (lin & 7) * 4;
            int k = k0 + kk4;
            int rem = EE - k;
            int bytes = rem >= 4 ? 16 : (rem > 0 ? rem * 4 : 0);
            const float* src = w_ih + (size_t)(n0 + col) * EE + (bytes ? k : 0);
            cp16z(smem_u32(&Bs[col * LDA + kk4]), src, bytes);
        }
        cp_commit();
    };

    float acc[2][4][4] = {};
    const int NKB = (EE + 31) / 32;  // 10
    load_tiles(0, 0);
    for (int kb = 0; kb < NKB; kb++) {
        if (kb + 1 < NKB) {
            load_tiles(kb + 1, (kb + 1) & 1);
            cp_wait<1>();
        } else {
            cp_wait<0>();
        }
        __syncthreads();
        const float* As = smem + (kb & 1) * XP_STAGE_FLOATS;
        compute_block_tf32(As, As + 128 * LDA, acc, wm, wn, g, tig);
        __syncthreads();
    }

    // epilogue -> g_gx2[t][cb][row][gate*16+hc], + biases
#pragma unroll
    for (int mt = 0; mt < 2; mt++) {
#pragma unroll
        for (int nt = 0; nt < 4; nt++) {
            int row0 = wm + mt * 16 + g;
            int col0 = wn + nt * 8 + 2 * tig;
            int j0 = n0 + col0;
            int gate = j0 >> 11;
            int q = j0 & 2047;
            int cb = q >> 4;
            int hc = q & 15;
            float bias0 = b_ih[j0] + b_hh[j0];
            float bias1 = b_ih[j0 + 1] + b_hh[j0 + 1];
            size_t base0 = (((size_t)t * 128 + cb) * 128 + row0) * 64 + gate * 16 + hc;
            g_gx2[base0] = acc[mt][nt][0] + bias0;
            g_gx2[base0 + 1] = acc[mt][nt][1] + bias1;
            size_t base2 = base0 + 8 * 64;
            g_gx2[base2] = acc[mt][nt][2] + bias0;
            g_gx2[base2 + 1] = acc[mt][nt][3] + bias1;
        }
    }
}

// ---------------- kernel 2: bf16 hi/lo LSTM step, 512 threads ---------------
// 128 CTAs; CTA cb computes D[128 batch, 64 cols], col = gate*16+hc, h-idx = cb*16+hc.
// 16 warps: 4 along M (32 rows each) x 4 along N (16 cols each).
// gates = h_hi*W_hi + h_hi*W_lo + h_lo*W_hi  (fp32 accumulate)
#define KC 64                                  // bf16 per row per chunk = 128 B
#define NCHUNK (HH / KC)                       // 32
#define AT_BYTES (128 * 128)                   // one A tile (hi or lo): 16 KB
#define BT_BYTES (64 * 128)                    // one B tile: 8 KB
#define STG_BYTES (2 * AT_BYTES + 2 * BT_BYTES)  // 49152
#define NSTG 3
#define STEP_SMEM_BYTES (NSTG * STG_BYTES)     // 147456
#define STEP_THREADS 512

__global__ void __launch_bounds__(STEP_THREADS) step_kernel(int t, float* __restrict__ d_out) {
    const uint32_t sbase = smem_u32(dyn_smem);
    const int tid = threadIdx.x;
    const int wid = tid >> 5, lane = tid & 31;
    const int cb = blockIdx.x;
    const int h0 = cb * 16;
    const int wm = (wid & 3) * 32;   // M group: 32 rows
    const int wn = (wid >> 2) * 16;  // N group: 16 cols

    auto issue_stage = [&](int c, int s) {
        uint32_t base = sbase + s * STG_BYTES;
        int k0 = c * KC;
#pragma unroll
        for (int i = 0; i < 2; i++) {
            int lin = tid + i * STEP_THREADS;
            int row = lin >> 3;
            int o16 = lin & 7;
            uint32_t sw = SMEM_SWZ128(row * 128 + o16 * 16);
            int gidx = row * HH + k0 + o16 * 8;
            cp16(base + sw, &g_h_hi[gidx]);
            cp16(base + AT_BYTES + sw, &g_h_lo[gidx]);
        }
        {
            int n = tid >> 3;
            int o16 = tid & 7;
            int j = (n >> 4) * HH + h0 + (n & 15);
            uint32_t sw = SMEM_SWZ128(n * 128 + o16 * 16);
            size_t gidx = (size_t)j * HH + k0 + o16 * 8;
            cp16(base + 2 * AT_BYTES + sw, &g_w_hi[gidx]);
            cp16(base + 2 * AT_BYTES + BT_BYTES + sw, &g_w_lo[gidx]);
        }
        cp_commit();
    };

    // per-lane ldmatrix coordinates
    const int arow = lane & 15;                        // A: row within 16-row tile
    const int acs = lane >> 4;                         // A: k-chunk select (0/1)
    const int brow = (lane & 7) + ((lane & 16) >> 1);  // B: row within 16-col group
    const int bcs = (lane >> 3) & 1;                   // B: k-chunk select

    float acc[2][2][4] = {};

    issue_stage(0, 0);
    issue_stage(1, 1);

    for (int kb = 0; kb < NCHUNK; kb++) {
        cp_wait<1>();
        __syncthreads();
        int kn = kb + 2;
        if (kn < NCHUNK) issue_stage(kn, kn % NSTG);
        const uint32_t base = sbase + (kb % NSTG) * STG_BYTES;

#pragma unroll
        for (int q = 0; q < 4; q++) {
            uint32_t ah[2][4], al[2][4], bh[4], bl[4];
#pragma unroll
            for (int mt = 0; mt < 2; mt++) {
                int row = wm + mt * 16 + arow;
                uint32_t sw = SMEM_SWZ128(row * 128 + (2 * q + acs) * 16);
                ldsm4(ah[mt], base + sw);
                ldsm4(al[mt], base + AT_BYTES + sw);
            }
            {
                int n = wn + brow;
                uint32_t sw = SMEM_SWZ128(n * 128 + (2 * q + bcs) * 16);
                ldsm4(bh, base + 2 * AT_BYTES + sw);
                ldsm4(bl, base + 2 * AT_BYTES + BT_BYTES + sw);
            }
#pragma unroll
            for (int mt = 0; mt < 2; mt++)
#pragma unroll
                for (int nt = 0; nt < 2; nt++) {
                    uint32_t b0h = bh[nt * 2], b1h = bh[nt * 2 + 1];
                    uint32_t b0l = bl[nt * 2], b1l = bl[nt * 2 + 1];
                    mma_bf16(acc[mt][nt], ah[mt], b0h, b1h);
                    mma_bf16(acc[mt][nt], ah[mt], b0l, b1l);
                    mma_bf16(acc[mt][nt], al[mt], b0h, b1h);
                }
        }
    }

    __syncthreads();

    // stage gates in smem: gsm[128][65] floats (33280 B)
    float* gsm = reinterpret_cast<float*>(dyn_smem);
    const int g8 = lane >> 2, tig = lane & 3;
#pragma unroll
    for (int mt = 0; mt < 2; mt++) {
#pragma unroll
        for (int nt = 0; nt < 2; nt++) {
            int row0 = wm + mt * 16 + g8;
            int col0 = wn + nt * 8 + 2 * tig;
            gsm[row0 * 65 + col0] = acc[mt][nt][0];
            gsm[row0 * 65 + col0 + 1] = acc[mt][nt][1];
            gsm[(row0 + 8) * 65 + col0] = acc[mt][nt][2];
            gsm[(row0 + 8) * 65 + col0 + 1] = acc[mt][nt][3];
        }
    }
    __syncthreads();

    // LSTM cell: 128 b x 16 h, 4 per thread (512 threads)
    const int b = tid >> 2;
    const int hh = (tid & 3) * 4;
    const float* __restrict__ gx = &g_gx2[(((size_t)t * 128 + cb) * 128 + b) * 64];
    float* __restrict__ cc = &g_c2[(cb * 128 + b) * 16];
#pragma unroll
    for (int i = 0; i < 4; i++) {
        int hc = hh + i;
        float xi = gsm[b * 65 + 0 * 16 + hc] + gx[0 * 16 + hc];
        float xf = gsm[b * 65 + 1 * 16 + hc] + gx[1 * 16 + hc];
        float xg = gsm[b * 65 + 2 * 16 + hc] + gx[2 * 16 + hc];
        float xo = gsm[b * 65 + 3 * 16 + hc] + gx[3 * 16 + hc];
        float ig = sigmoidf_(xi);
        float fg = sigmoidf_(xf);
        float gg = tanhf(xg);
        float og = sigmoidf_(xo);
        float cn = fg * cc[hc] + ig * gg;
        cc[hc] = cn;
        float hv = og * tanhf(cn);
        __nv_bfloat16 hi = __float2bfloat16(hv);
        g_h_hi[b * HH + h0 + hc] = hi;
        g_h_lo[b * HH + h0 + hc] = __float2bfloat16(hv - __bfloat162float(hi));
        if (t == TT - 1) d_out[b * HH + h0 + hc] = hv;
    }
}

// ---------------- launch ----------------------------------------------------
extern "C" void kernel_launch(void* const* d_in, const int* in_sizes, int n_in, void* d_out,
                              int out_size) {
    const int* input = (const int*)d_in[0];
    const float* embed = (const float*)d_in[1];
    const float* w_ih = (const float*)d_in[2];
    const float* w_hh = (const float*)d_in[3];
    const float* b_ih = (const float*)d_in[4];
    const float* b_hh = (const float*)d_in[5];
    float* out = (float*)d_out;

    cudaFuncSetAttribute(xproj_kernel, cudaFuncAttributeMaxDynamicSharedMemorySize, XP_SMEM_BYTES);
    cudaFuncSetAttribute(step_kernel, cudaFuncAttributeMaxDynamicSharedMemorySize,
                         STEP_SMEM_BYTES);

    zero_kernel<<<(BB * HH + 255) / 256, 256>>>();
    wsplit_kernel<<<(int)(((size_t)G4 * HH / 4 + 255) / 256), 256>>>(w_hh);
    xproj_kernel<<<dim3(TT, 128), 256, XP_SMEM_BYTES>>>(input, embed, w_ih, b_ih, b_hh);
    for (int t = 0; t < TT; t++) {
        step_kernel<<<128, STEP_THREADS, STEP_SMEM_BYTES>>>(t, out);
    }
}

// round 8
// speedup vs baseline: 2.5679x; 2.5679x over previous
#include <cuda_runtime.h>
#include <cuda_fp16.h>
#include <cstdint>

#define BB 128          // batch
#define TT 64           // time steps
#define EE 300          // embed dim
#define HH 2048         // hidden
#define G4 8192         // 4*H

// ---------------- scratch (device globals; no allocation allowed) ----------
__device__ float g_gx2[(size_t)TT * 128 * 128 * 64];   // [t][cb][b][gate*16+hc]
__device__ __half g_w16[(size_t)G4 * HH];              // W_hh fp16
__device__ __half g_h16[BB * HH];                      // hidden state fp16
__device__ float g_c2[BB * HH];                        // cell state [cb][b][16]

// single dynamic smem symbol shared by all kernels
extern __shared__ __align__(1024) char dyn_smem[];

// ---------------- helpers --------------------------------------------------
__device__ __forceinline__ uint32_t smem_u32(const void* p) {
    return (uint32_t)__cvta_generic_to_shared(p);
}
__device__ __forceinline__ void cp16(uint32_t dst, const void* src) {
    asm volatile("cp.async.ca.shared.global [%0], [%1], 16;\n" ::"r"(dst), "l"(src));
}
__device__ __forceinline__ void cp16z(uint32_t dst, const void* src, int bytes) {
    asm volatile("cp.async.ca.shared.global [%0], [%1], 16, %2;\n" ::"r"(dst), "l"(src), "r"(bytes));
}
__device__ __forceinline__ void cp_commit() { asm volatile("cp.async.commit_group;\n"); }
template <int N> __device__ __forceinline__ void cp_wait() {
    asm volatile("cp.async.wait_group %0;\n" ::"n"(N));
}
__device__ __forceinline__ void mma_fp16(float c[4], const uint32_t a[4], uint32_t b0,
                                         uint32_t b1) {
    asm volatile(
        "mma.sync.aligned.m16n8k16.row.col.f32.f16.f16.f32 "
        "{%0,%1,%2,%3},{%4,%5,%6,%7},{%8,%9},{%0,%1,%2,%3};\n"
        : "+f"(c[0]), "+f"(c[1]), "+f"(c[2]), "+f"(c[3])
        : "r"(a[0]), "r"(a[1]), "r"(a[2]), "r"(a[3]), "r"(b0), "r"(b1));
}
__device__ __forceinline__ void ldsm4(uint32_t r[4], uint32_t addr) {
    asm volatile("ldmatrix.sync.aligned.m8n8.x4.shared.b16 {%0,%1,%2,%3}, [%4];"
                 : "=r"(r[0]), "=r"(r[1]), "=r"(r[2]), "=r"(r[3])
                 : "r"(addr));
}
__device__ __forceinline__ float sigmoidf_(float x) { return 1.0f / (1.0f + __expf(-x)); }

#define SMEM_SWZ128(x) ((x) ^ (((x) >> 3) & 0x70))

// ---------------- init / W convert ------------------------------------------
__global__ void zero_kernel() {
    int i = blockIdx.x * blockDim.x + threadIdx.x;
    if (i < BB * HH) {
        g_h16[i] = __float2half(0.f);
        g_c2[i] = 0.f;
    }
}

__global__ void wconv_kernel(const float* __restrict__ w) {
    size_t i = ((size_t)blockIdx.x * blockDim.x + threadIdx.x) * 4;
    if (i < (size_t)G4 * HH) {
        float4 v = *reinterpret_cast<const float4*>(w + i);
        g_w16[i] = __float2half(v.x);
        g_w16[i + 1] = __float2half(v.y);
        g_w16[i + 2] = __float2half(v.z);
        g_w16[i + 3] = __float2half(v.w);
    }
}

// ---------------- kernel 1: embedding gather + input projection (tf32 SIMT) -
#define LDA 36
#define XP_STAGE_FLOATS ((128 + 64) * LDA)
#define XP_SMEM_BYTES (2 * XP_STAGE_FLOATS * 4)

__device__ __forceinline__ void compute_block_tf32(const float* __restrict__ As,
                                                   const float* __restrict__ Bs,
                                                   float acc[2][4][4], int wm, int wn, int g,
                                                   int tig) {
#pragma unroll
    for (int k8 = 0; k8 < 32; k8 += 8) {
        uint32_t a[2][4];
#pragma unroll
        for (int mt = 0; mt < 2; mt++) {
            int r = wm + mt * 16;
            a[mt][0] = __float_as_uint(As[(r + g) * LDA + k8 + tig]);
            a[mt][1] = __float_as_uint(As[(r + g + 8) * LDA + k8 + tig]);
            a[mt][2] = __float_as_uint(As[(r + g) * LDA + k8 + tig + 4]);
            a[mt][3] = __float_as_uint(As[(r + g + 8) * LDA + k8 + tig + 4]);
        }
        uint32_t b[4][2];
#pragma unroll
        for (int nt = 0; nt < 4; nt++) {
            int cc = wn + nt * 8 + g;
            b[nt][0] = __float_as_uint(Bs[cc * LDA + k8 + tig]);
            b[nt][1] = __float_as_uint(Bs[cc * LDA + k8 + tig + 4]);
        }
#pragma unroll
        for (int mt = 0; mt < 2; mt++)
#pragma unroll
            for (int nt = 0; nt < 4; nt++) {
                float* c = acc[mt][nt];
                asm volatile(
                    "mma.sync.aligned.m16n8k8.row.col.f32.tf32.tf32.f32 "
                    "{%0,%1,%2,%3},{%4,%5,%6,%7},{%8,%9},{%0,%1,%2,%3};\n"
                    : "+f"(c[0]), "+f"(c[1]), "+f"(c[2]), "+f"(c[3])
                    : "r"(a[mt][0]), "r"(a[mt][1]), "r"(a[mt][2]), "r"(a[mt][3]), "r"(b[nt][0]),
                      "r"(b[nt][1]));
            }
    }
}

__global__ void __launch_bounds__(256) xproj_kernel(const int* __restrict__ input,
                                                    const float* __restrict__ embed,
                                                    const float* __restrict__ w_ih,
                                                    const float* __restrict__ b_ih,
                                                    const float* __restrict__ b_hh) {
    float* smem = reinterpret_cast<float*>(dyn_smem);
    __shared__ int tok[128];

    const int tid = threadIdx.x;
    const int t = blockIdx.x;
    const int n0 = blockIdx.y * 64;

    if (tid < 128) tok[tid] = input[tid * TT + t];
    __syncthreads();

    const int wid = tid >> 5, lane = tid & 31;
    const int wm = (wid & 3) * 32, wn = (wid >> 2) * 32;
    const int g = lane >> 2, tig = lane & 3;

    auto load_tiles = [&](int kb, int s) {
        float* As = smem + s * XP_STAGE_FLOATS;
        float* Bs = As + 128 * LDA;
        int k0 = kb * 32;
#pragma unroll
        for (int i = 0; i < 4; i++) {
            int lin = tid + i * 256;
            int row = lin >> 3;
            int kk4 = (lin & 7) * 4;
            int k = k0 + kk4;
            int rem = EE - k;
            int bytes = rem >= 4 ? 16 : (rem > 0 ? rem * 4 : 0);
            const float* src = embed + (size_t)tok[row] * EE + (bytes ? k : 0);
            cp16z(smem_u32(&As[row * LDA + kk4]), src, bytes);
        }
#pragma unroll
        for (int i = 0; i < 2; i++) {
            int lin = tid + i * 256;
            int col = lin >> 3;
            int kk4 = (lin & 7) * 4;
            int k = k0 + kk4;
            int rem = EE - k;
            int bytes = rem >= 4 ? 16 : (rem > 0 ? rem * 4 : 0);
            const float* src = w_ih + (size_t)(n0 + col) * EE + (bytes ? k : 0);
            cp16z(smem_u32(&Bs[col * LDA + kk4]), src, bytes);
        }
        cp_commit();
    };

    float acc[2][4][4] = {};
    const int NKB = (EE + 31) / 32;  // 10
    load_tiles(0, 0);
    for (int kb = 0; kb < NKB; kb++) {
        if (kb + 1 < NKB) {
            load_tiles(kb + 1, (kb + 1) & 1);
            cp_wait<1>();
        } else {
            cp_wait<0>();
        }
        __syncthreads();
        const float* As = smem + (kb & 1) * XP_STAGE_FLOATS;
        compute_block_tf32(As, As + 128 * LDA, acc, wm, wn, g, tig);
        __syncthreads();
    }

    // epilogue -> g_gx2[t][cb][row][gate*16+hc], + biases
#pragma unroll
    for (int mt = 0; mt < 2; mt++) {
#pragma unroll
        for (int nt = 0; nt < 4; nt++) {
            int row0 = wm + mt * 16 + g;
            int col0 = wn + nt * 8 + 2 * tig;
            int j0 = n0 + col0;
            int gate = j0 >> 11;
            int q = j0 & 2047;
            int cb = q >> 4;
            int hc = q & 15;
            float bias0 = b_ih[j0] + b_hh[j0];
            float bias1 = b_ih[j0 + 1] + b_hh[j0 + 1];
            size_t base0 = (((size_t)t * 128 + cb) * 128 + row0) * 64 + gate * 16 + hc;
            g_gx2[base0] = acc[mt][nt][0] + bias0;
            g_gx2[base0 + 1] = acc[mt][nt][1] + bias1;
            size_t base2 = base0 + 8 * 64;
            g_gx2[base2] = acc[mt][nt][2] + bias0;
            g_gx2[base2 + 1] = acc[mt][nt][3] + bias1;
        }
    }
}

// ---------------- kernel 2: fp16 LSTM step (single-term, ldmatrix + mma) ----
// 128 CTAs; CTA cb computes D[128 batch, 64 cols], col = gate*16+hc, h-idx = cb*16+hc.
// 8 warps: 4 along M (32 rows) x 2 along N (32 cols).  gates = h16 @ W16^T, fp32 accum.
#define KC 64                                  // fp16 per row per chunk = 128 B
#define NCHUNK (HH / KC)                       // 32
#define AT_BYTES (128 * 128)                   // A tile: 16 KB
#define BT_BYTES (64 * 128)                    // B tile: 8 KB
#define STG_BYTES (AT_BYTES + BT_BYTES)        // 24576
#define NSTG 6
#define STEP_SMEM_BYTES (NSTG * STG_BYTES)     // 147456
#define STEP_THREADS 256

__global__ void __launch_bounds__(STEP_THREADS) step_kernel(int t, float* __restrict__ d_out) {
    const uint32_t sbase = smem_u32(dyn_smem);
    const int tid = threadIdx.x;
    const int wid = tid >> 5, lane = tid & 31;
    const int cb = blockIdx.x;
    const int h0 = cb * 16;
    const int wm = (wid & 3) * 32, wn = (wid >> 2) * 32;

    auto issue_stage = [&](int c, int s) {
        uint32_t base = sbase + s * STG_BYTES;
        int k0 = c * KC;
#pragma unroll
        for (int i = 0; i < 4; i++) {
            int lin = tid + i * STEP_THREADS;
            int row = lin >> 3;
            int o16 = lin & 7;
            uint32_t sw = SMEM_SWZ128(row * 128 + o16 * 16);
            cp16(base + sw, &g_h16[row * HH + k0 + o16 * 8]);
        }
#pragma unroll
        for (int i = 0; i < 2; i++) {
            int lin = tid + i * STEP_THREADS;
            int n = lin >> 3;
            int o16 = lin & 7;
            int j = (n >> 4) * HH + h0 + (n & 15);
            uint32_t sw = SMEM_SWZ128(n * 128 + o16 * 16);
            cp16(base + AT_BYTES + sw, &g_w16[(size_t)j * HH + k0 + o16 * 8]);
        }
        cp_commit();
    };

    // per-lane ldmatrix coordinates
    const int arow = lane & 15;                        // A: row within 16-row tile
    const int acs = lane >> 4;                         // A: k-chunk select (0/1)
    const int brow = (lane & 7) + ((lane & 16) >> 1);  // B: row within 16-row group
    const int bcs = (lane >> 3) & 1;                   // B: k-chunk select

    float acc[2][4][4] = {};

#pragma unroll
    for (int p = 0; p < NSTG - 1; p++) issue_stage(p, p);

    for (int kb = 0; kb < NCHUNK; kb++) {
        cp_wait<NSTG - 2>();
        __syncthreads();
        int kn = kb + NSTG - 1;
        if (kn < NCHUNK) issue_stage(kn, kn % NSTG);
        else cp_commit();  // keep group count exact in tail
        const uint32_t base = sbase + (kb % NSTG) * STG_BYTES;

#pragma unroll
        for (int q = 0; q < 4; q++) {
            uint32_t a[2][4], b[2][4];
#pragma unroll
            for (int mt = 0; mt < 2; mt++) {
                int row = wm + mt * 16 + arow;
                uint32_t sw = SMEM_SWZ128(row * 128 + (2 * q + acs) * 16);
                ldsm4(a[mt], base + sw);
            }
#pragma unroll
            for (int nh = 0; nh < 2; nh++) {
                int n = wn + nh * 16 + brow;
                uint32_t sw = SMEM_SWZ128(n * 128 + (2 * q + bcs) * 16);
                ldsm4(b[nh], base + AT_BYTES + sw);
            }
#pragma unroll
            for (int mt = 0; mt < 2; mt++)
#pragma unroll
                for (int nt = 0; nt < 4; nt++)
                    mma_fp16(acc[mt][nt], a[mt], b[nt >> 1][(nt & 1) * 2],
                             b[nt >> 1][(nt & 1) * 2 + 1]);
        }
    }

    __syncthreads();

    // stage gates in smem: gsm[128][65] floats (33280 B)
    float* gsm = reinterpret_cast<float*>(dyn_smem);
    const int g8 = lane >> 2, tig = lane & 3;
#pragma unroll
    for (int mt = 0; mt < 2; mt++) {
#pragma unroll
        for (int nt = 0; nt < 4; nt++) {
            int row0 = wm + mt * 16 + g8;
            int col0 = wn + nt * 8 + 2 * tig;
            gsm[row0 * 65 + col0] = acc[mt][nt][0];
            gsm[row0 * 65 + col0 + 1] = acc[mt][nt][1];
            gsm[(row0 + 8) * 65 + col0] = acc[mt][nt][2];
            gsm[(row0 + 8) * 65 + col0 + 1] = acc[mt][nt][3];
        }
    }
    __syncthreads();

    // LSTM cell: 128 b x 16 h, 8 per thread (256 threads)
    const int b = tid >> 1;
    const int hh = (tid & 1) * 8;
    const float* __restrict__ gx = &g_gx2[(((size_t)t * 128 + cb) * 128 + b) * 64];
    float* __restrict__ cc = &g_c2[(cb * 128 + b) * 16];
#pragma unroll
    for (int i = 0; i < 8; i++) {
        int hc = hh + i;
        float xi = gsm[b * 65 + 0 * 16 + hc] + gx[0 * 16 + hc];
        float xf = gsm[b * 65 + 1 * 16 + hc] + gx[1 * 16 + hc];
        float xg = gsm[b * 65 + 2 * 16 + hc] + gx[2 * 16 + hc];
        float xo = gsm[b * 65 + 3 * 16 + hc] + gx[3 * 16 + hc];
        float ig = sigmoidf_(xi);
        float fg = sigmoidf_(xf);
        float gg = tanhf(xg);
        float og = sigmoidf_(xo);
        float cn = fg * cc[hc] + ig * gg;
        cc[hc] = cn;
        float hv = og * tanhf(cn);
        g_h16[b * HH + h0 + hc] = __float2half(hv);
        if (t == TT - 1) d_out[b * HH + h0 + hc] = hv;
    }
}

// ---------------- launch ----------------------------------------------------
extern "C" void kernel_launch(void* const* d_in, const int* in_sizes, int n_in, void* d_out,
                              int out_size) {
    const int* input = (const int*)d_in[0];
    const float* embed = (const float*)d_in[1];
    const float* w_ih = (const float*)d_in[2];
    const float* w_hh = (const float*)d_in[3];
    const float* b_ih = (const float*)d_in[4];
    const float* b_hh = (const float*)d_in[5];
    float* out = (float*)d_out;

    cudaFuncSetAttribute(xproj_kernel, cudaFuncAttributeMaxDynamicSharedMemorySize, XP_SMEM_BYTES);
    cudaFuncSetAttribute(step_kernel, cudaFuncAttributeMaxDynamicSharedMemorySize,
                         STEP_SMEM_BYTES);

    zero_kernel<<<(BB * HH + 255) / 256, 256>>>();
    wconv_kernel<<<(int)(((size_t)G4 * HH / 4 + 255) / 256), 256>>>(w_hh);
    xproj_kernel<<<dim3(TT, 128), 256, XP_SMEM_BYTES>>>(input, embed, w_ih, b_ih, b_hh);
    for (int t = 0; t < TT; t++) {
        step_kernel<<<128, STEP_THREADS, STEP_SMEM_BYTES>>>(t, out);
    }
}

// round 9
// speedup vs baseline: 2.7965x; 1.0890x over previous
#include <cuda_runtime.h>
#include <cuda_fp16.h>
#include <cstdint>

#define BB 128          // batch
#define TT 64           // time steps
#define EE 300          // embed dim
#define HH 2048         // hidden
#define G4 8192         // 4*H

// ---------------- scratch (device globals; no allocation allowed) ----------
__device__ float g_gx2[(size_t)TT * 128 * 128 * 64];   // [t][cb][b][gate*16+hc]
__device__ __half g_w16[(size_t)G4 * HH];              // W_hh fp16
__device__ __half g_ha[BB * HH];                       // hidden state ping
__device__ __half g_hb[BB * HH];                       // hidden state pong
__device__ float g_c2[BB * HH];                        // cell state [cb][b][16]
__device__ unsigned g_bar;                             // persistent-kernel barrier

// single dynamic smem symbol shared by all kernels
extern __shared__ __align__(1024) char dyn_smem[];

// ---------------- helpers --------------------------------------------------
__device__ __forceinline__ uint32_t smem_u32(const void* p) {
    return (uint32_t)__cvta_generic_to_shared(p);
}
__device__ __forceinline__ void cp16(uint32_t dst, const void* src) {
    asm volatile("cp.async.cg.shared.global [%0], [%1], 16;\n" ::"r"(dst), "l"(src));
}
__device__ __forceinline__ void cp16z(uint32_t dst, const void* src, int bytes) {
    asm volatile("cp.async.ca.shared.global [%0], [%1], 16, %2;\n" ::"r"(dst), "l"(src), "r"(bytes));
}
__device__ __forceinline__ void cp_commit() { asm volatile("cp.async.commit_group;\n"); }
template <int N> __device__ __forceinline__ void cp_wait() {
    asm volatile("cp.async.wait_group %0;\n" ::"n"(N));
}
__device__ __forceinline__ void mma_fp16(float c[4], const uint32_t a[4], uint32_t b0,
                                         uint32_t b1) {
    asm volatile(
        "mma.sync.aligned.m16n8k16.row.col.f32.f16.f16.f32 "
        "{%0,%1,%2,%3},{%4,%5,%6,%7},{%8,%9},{%0,%1,%2,%3};\n"
        : "+f"(c[0]), "+f"(c[1]), "+f"(c[2]), "+f"(c[3])
        : "r"(a[0]), "r"(a[1]), "r"(a[2]), "r"(a[3]), "r"(b0), "r"(b1));
}
__device__ __forceinline__ void ldsm4(uint32_t r[4], uint32_t addr) {
    asm volatile("ldmatrix.sync.aligned.m8n8.x4.shared.b16 {%0,%1,%2,%3}, [%4];"
                 : "=r"(r[0]), "=r"(r[1]), "=r"(r[2]), "=r"(r[3])
                 : "r"(addr));
}
__device__ __forceinline__ float sigmoidf_(float x) { return 1.0f / (1.0f + __expf(-x)); }

#define SMEM_SWZ128(x) ((x) ^ (((x) >> 3) & 0x70))

// ---------------- init / W convert ------------------------------------------
__global__ void zero_kernel() {
    int i = blockIdx.x * blockDim.x + threadIdx.x;
    if (i < BB * HH) {
        g_ha[i] = __float2half(0.f);
        g_c2[i] = 0.f;
    }
    if (i == 0) g_bar = 0u;
}

__global__ void wconv_kernel(const float* __restrict__ w) {
    size_t i = ((size_t)blockIdx.x * blockDim.x + threadIdx.x) * 4;
    if (i < (size_t)G4 * HH) {
        float4 v = *reinterpret_cast<const float4*>(w + i);
        g_w16[i] = __float2half(v.x);
        g_w16[i + 1] = __float2half(v.y);
        g_w16[i + 2] = __float2half(v.z);
        g_w16[i + 3] = __float2half(v.w);
    }
}

// ---------------- kernel 1: embedding gather + input projection (tf32 SIMT) -
#define LDA 36
#define XP_STAGE_FLOATS ((128 + 64) * LDA)
#define XP_SMEM_BYTES (2 * XP_STAGE_FLOATS * 4)

__device__ __forceinline__ void compute_block_tf32(const float* __restrict__ As,
                                                   const float* __restrict__ Bs,
                                                   float acc[2][4][4], int wm, int wn, int g,
                                                   int tig) {
#pragma unroll
    for (int k8 = 0; k8 < 32; k8 += 8) {
        uint32_t a[2][4];
#pragma unroll
        for (int mt = 0; mt < 2; mt++) {
            int r = wm + mt * 16;
            a[mt][0] = __float_as_uint(As[(r + g) * LDA + k8 + tig]);
            a[mt][1] = __float_as_uint(As[(r + g + 8) * LDA + k8 + tig]);
            a[mt][2] = __float_as_uint(As[(r + g) * LDA + k8 + tig + 4]);
            a[mt][3] = __float_as_uint(As[(r + g + 8) * LDA + k8 + tig + 4]);
        }
        uint32_t b[4][2];
#pragma unroll
        for (int nt = 0; nt < 4; nt++) {
            int cc = wn + nt * 8 + g;
            b[nt][0] = __float_as_uint(Bs[cc * LDA + k8 + tig]);
            b[nt][1] = __float_as_uint(Bs[cc * LDA + k8 + tig + 4]);
        }
#pragma unroll
        for (int mt = 0; mt < 2; mt++)
#pragma unroll
            for (int nt = 0; nt < 4; nt++) {
                float* c = acc[mt][nt];
                asm volatile(
                    "mma.sync.aligned.m16n8k8.row.col.f32.tf32.tf32.f32 "
                    "{%0,%1,%2,%3},{%4,%5,%6,%7},{%8,%9},{%0,%1,%2,%3};\n"
                    : "+f"(c[0]), "+f"(c[1]), "+f"(c[2]), "+f"(c[3])
                    : "r"(a[mt][0]), "r"(a[mt][1]), "r"(a[mt][2]), "r"(a[mt][3]), "r"(b[nt][0]),
                      "r"(b[nt][1]));
            }
    }
}

__global__ void __launch_bounds__(256) xproj_kernel(const int* __restrict__ input,
                                                    const float* __restrict__ embed,
                                                    const float* __restrict__ w_ih,
                                                    const float* __restrict__ b_ih,
                                                    const float* __restrict__ b_hh) {
    float* smem = reinterpret_cast<float*>(dyn_smem);
    __shared__ int tok[128];

    const int tid = threadIdx.x;
    const int t = blockIdx.x;
    const int n0 = blockIdx.y * 64;

    if (tid < 128) tok[tid] = input[tid * TT + t];
    __syncthreads();

    const int wid = tid >> 5, lane = tid & 31;
    const int wm = (wid & 3) * 32, wn = (wid >> 2) * 32;
    const int g = lane >> 2, tig = lane & 3;

    auto load_tiles = [&](int kb, int s) {
        float* As = smem + s * XP_STAGE_FLOATS;
        float* Bs = As + 128 * LDA;
        int k0 = kb * 32;
#pragma unroll
        for (int i = 0; i < 4; i++) {
            int lin = tid + i * 256;
            int row = lin >> 3;
            int kk4 = (lin & 7) * 4;
            int k = k0 + kk4;
            int rem = EE - k;
            int bytes = rem >= 4 ? 16 : (rem > 0 ? rem * 4 : 0);
            const float* src = embed + (size_t)tok[row] * EE + (bytes ? k : 0);
            cp16z(smem_u32(&As[row * LDA + kk4]), src, bytes);
        }
#pragma unroll
        for (int i = 0; i < 2; i++) {
            int lin = tid + i * 256;
            int col = lin >> 3;
            int kk4 = (lin & 7) * 4;
            int k = k0 + kk4;
            int rem = EE - k;
            int bytes = rem >= 4 ? 16 : (rem > 0 ? rem * 4 : 0);
            const float* src = w_ih + (size_t)(n0 + col) * EE + (bytes ? k : 0);
            cp16z(smem_u32(&Bs[col * LDA + kk4]), src, bytes);
        }
        cp_commit();
    };

    float acc[2][4][4] = {};
    const int NKB = (EE + 31) / 32;  // 10
    load_tiles(0, 0);
    for (int kb = 0; kb < NKB; kb++) {
        if (kb + 1 < NKB) {
            load_tiles(kb + 1, (kb + 1) & 1);
            cp_wait<1>();
        } else {
            cp_wait<0>();
        }
        __syncthreads();
        const float* As = smem + (kb & 1) * XP_STAGE_FLOATS;
        compute_block_tf32(As, As + 128 * LDA, acc, wm, wn, g, tig);
        __syncthreads();
    }

    // epilogue -> g_gx2[t][cb][row][gate*16+hc], + biases
#pragma unroll
    for (int mt = 0; mt < 2; mt++) {
#pragma unroll
        for (int nt = 0; nt < 4; nt++) {
            int row0 = wm + mt * 16 + g;
            int col0 = wn + nt * 8 + 2 * tig;
            int j0 = n0 + col0;
            int gate = j0 >> 11;
            int q = j0 & 2047;
            int cb = q >> 4;
            int hc = q & 15;
            float bias0 = b_ih[j0] + b_hh[j0];
            float bias1 = b_ih[j0 + 1] + b_hh[j0 + 1];
            size_t base0 = (((size_t)t * 128 + cb) * 128 + row0) * 64 + gate * 16 + hc;
            g_gx2[base0] = acc[mt][nt][0] + bias0;
            g_gx2[base0 + 1] = acc[mt][nt][1] + bias1;
            size_t base2 = base0 + 8 * 64;
            g_gx2[base2] = acc[mt][nt][2] + bias0;
            g_gx2[base2 + 1] = acc[mt][nt][3] + bias1;
        }
    }
}

// ---------------- kernel 2: persistent fp16 LSTM (all 64 steps) -------------
// 128 resident CTAs; CTA cb computes D[128 batch, 64 cols], col = gate*16+hc.
// Per t: gates = h16 @ W16^T (fp32 accum), fused cell, global barrier.
#define KC 64                                  // fp16 per row per chunk = 128 B
#define NCHUNK (HH / KC)                       // 32
#define AT_BYTES (128 * 128)                   // A tile: 16 KB
#define BT_BYTES (64 * 128)                    // B tile: 8 KB
#define STG_BYTES (AT_BYTES + BT_BYTES)        // 24576
#define NSTG 6
#define STEP_SMEM_BYTES (NSTG * STG_BYTES)     // 147456
#define STEP_THREADS 256

__global__ void __launch_bounds__(STEP_THREADS) step_persistent(float* __restrict__ d_out) {
    const uint32_t sbase = smem_u32(dyn_smem);
    const int tid = threadIdx.x;
    const int wid = tid >> 5, lane = tid & 31;
    const int cb = blockIdx.x;
    const int h0 = cb * 16;
    const int wm = (wid & 3) * 32, wn = (wid >> 2) * 32;

    // per-lane ldmatrix coordinates
    const int arow = lane & 15;                        // A: row within 16-row tile
    const int acs = lane >> 4;                         // A: k-chunk select (0/1)
    const int brow = (lane & 7) + ((lane & 16) >> 1);  // B: row within 16-row group
    const int bcs = (lane >> 3) & 1;                   // B: k-chunk select
    const int g8 = lane >> 2, tig = lane & 3;

    for (int t = 0; t < TT; t++) {
        const __half* __restrict__ h_in = (t & 1) ? g_hb : g_ha;
        __half* __restrict__ h_out = (t & 1) ? g_ha : g_hb;

        auto issue_stage = [&](int c, int s) {
            uint32_t base = sbase + s * STG_BYTES;
            int k0 = c * KC;
#pragma unroll
            for (int i = 0; i < 4; i++) {
                int lin = tid + i * STEP_THREADS;
                int row = lin >> 3;
                int o16 = lin & 7;
                uint32_t sw = SMEM_SWZ128(row * 128 + o16 * 16);
                cp16(base + sw, &h_in[row * HH + k0 + o16 * 8]);
            }
#pragma unroll
            for (int i = 0; i < 2; i++) {
                int lin = tid + i * STEP_THREADS;
                int n = lin >> 3;
                int o16 = lin & 7;
                int j = (n >> 4) * HH + h0 + (n & 15);
                uint32_t sw = SMEM_SWZ128(n * 128 + o16 * 16);
                cp16(base + AT_BYTES + sw, &g_w16[(size_t)j * HH + k0 + o16 * 8]);
            }
            cp_commit();
        };

        float acc[2][4][4] = {};

#pragma unroll
        for (int p = 0; p < NSTG - 1; p++) issue_stage(p, p);

        for (int kb = 0; kb < NCHUNK; kb++) {
            cp_wait<NSTG - 2>();
            __syncthreads();
            int kn = kb + NSTG - 1;
            if (kn < NCHUNK) issue_stage(kn, kn % NSTG);
            else cp_commit();  // keep group count exact in tail
            const uint32_t base = sbase + (kb % NSTG) * STG_BYTES;

            // register double-buffered fragments: load q+1 while mma q
            uint32_t a[2][2][4], b[2][2][4];
            auto load_frags = [&](int q, int pb) {
#pragma unroll
                for (int mt = 0; mt < 2; mt++) {
                    int row = wm + mt * 16 + arow;
                    uint32_t sw = SMEM_SWZ128(row * 128 + (2 * q + acs) * 16);
                    ldsm4(a[pb][mt], base + sw);
                }
#pragma unroll
                for (int nh = 0; nh < 2; nh++) {
                    int n = wn + nh * 16 + brow;
                    uint32_t sw = SMEM_SWZ128(n * 128 + (2 * q + bcs) * 16);
                    ldsm4(b[pb][nh], base + AT_BYTES + sw);
                }
            };
            load_frags(0, 0);
#pragma unroll
            for (int q = 0; q < 4; q++) {
                if (q < 3) load_frags(q + 1, (q + 1) & 1);
                const int pb = q & 1;
#pragma unroll
                for (int mt = 0; mt < 2; mt++)
#pragma unroll
                    for (int nt = 0; nt < 4; nt++)
                        mma_fp16(acc[mt][nt], a[pb][mt], b[pb][nt >> 1][(nt & 1) * 2],
                                 b[pb][nt >> 1][(nt & 1) * 2 + 1]);
            }
        }

        __syncthreads();

        // stage gates in smem: gsm[128][65] floats (33280 B, stages 0-1)
        float* gsm = reinterpret_cast<float*>(dyn_smem);
#pragma unroll
        for (int mt = 0; mt < 2; mt++) {
#pragma unroll
            for (int nt = 0; nt < 4; nt++) {
                int row0 = wm + mt * 16 + g8;
                int col0 = wn + nt * 8 + 2 * tig;
                gsm[row0 * 65 + col0] = acc[mt][nt][0];
                gsm[row0 * 65 + col0 + 1] = acc[mt][nt][1];
                gsm[(row0 + 8) * 65 + col0] = acc[mt][nt][2];
                gsm[(row0 + 8) * 65 + col0 + 1] = acc[mt][nt][3];
            }
        }
        __syncthreads();

        // LSTM cell: 128 b x 16 h, 8 per thread
        {
            const int b = tid >> 1;
            const int hh = (tid & 1) * 8;
            const float* __restrict__ gx = &g_gx2[(((size_t)t * 128 + cb) * 128 + b) * 64];
            float* __restrict__ cc = &g_c2[(cb * 128 + b) * 16];
#pragma unroll
            for (int i = 0; i < 8; i++) {
                int hc = hh + i;
                float xi = gsm[b * 65 + 0 * 16 + hc] + gx[0 * 16 + hc];
                float xf = gsm[b * 65 + 1 * 16 + hc] + gx[1 * 16 + hc];
                float xg = gsm[b * 65 + 2 * 16 + hc] + gx[2 * 16 + hc];
                float xo = gsm[b * 65 + 3 * 16 + hc] + gx[3 * 16 + hc];
                float ig = sigmoidf_(xi);
                float fg = sigmoidf_(xf);
                float gg = tanhf(xg);
                float og = sigmoidf_(xo);
                float cn = fg * cc[hc] + ig * gg;
                cc[hc] = cn;
                float hv = og * tanhf(cn);
                h_out[b * HH + h0 + hc] = __float2half(hv);
                if (t == TT - 1) d_out[b * HH + h0 + hc] = hv;
            }
        }

        // ---- global barrier (all 128 CTAs) ----
        if (t < TT - 1) {
            __syncthreads();
            __threadfence();
            if (tid == 0) {
                atomicAdd(&g_bar, 1u);
                const unsigned target = 128u * (unsigned)(t + 1);
                unsigned v;
                do {
                    asm volatile("ld.acquire.gpu.global.u32 %0, [%1];" : "=r"(v) : "l"(&g_bar));
                    if (v < target) __nanosleep(64);
                } while (v < target);
            }
            __syncthreads();
        }
    }
}

// ---------------- launch ----------------------------------------------------
extern "C" void kernel_launch(void* const* d_in, const int* in_sizes, int n_in, void* d_out,
                              int out_size) {
    const int* input = (const int*)d_in[0];
    const float* embed = (const float*)d_in[1];
    const float* w_ih = (const float*)d_in[2];
    const float* w_hh = (const float*)d_in[3];
    const float* b_ih = (const float*)d_in[4];
    const float* b_hh = (const float*)d_in[5];
    float* out = (float*)d_out;

    cudaFuncSetAttribute(xproj_kernel, cudaFuncAttributeMaxDynamicSharedMemorySize, XP_SMEM_BYTES);
    cudaFuncSetAttribute(step_persistent, cudaFuncAttributeMaxDynamicSharedMemorySize,
                         STEP_SMEM_BYTES);

    zero_kernel<<<(BB * HH + 255) / 256, 256>>>();
    wconv_kernel<<<(int)(((size_t)G4 * HH / 4 + 255) / 256), 256>>>(w_hh);
    xproj_kernel<<<dim3(TT, 128), 256, XP_SMEM_BYTES>>>(input, embed, w_ih, b_ih, b_hh);
    step_persistent<<<128, STEP_THREADS, STEP_SMEM_BYTES>>>(out);
}

// round 10
// speedup vs baseline: 3.0603x; 1.0943x over previous
#include <cuda_runtime.h>
#include <cuda_fp16.h>
#include <cstdint>

#define BB 128          // batch
#define TT 64           // time steps
#define EE 300          // embed dim
#define HH 2048         // hidden
#define G4 8192         // 4*H

// ---------------- scratch (device globals; no allocation allowed) ----------
__device__ float g_gx2[(size_t)TT * 128 * 128 * 64];   // [t][cb][b][gate*16+hc]
__device__ __half g_w16[(size_t)G4 * HH];              // W_hh fp16
__device__ __half g_ha[BB * HH];                       // hidden state ping
__device__ __half g_hb[BB * HH];                       // hidden state pong
__device__ float g_c2[BB * HH];                        // cell state [cb][b][16]
__device__ unsigned g_bar;                             // persistent-kernel barrier

// single dynamic smem symbol shared by all kernels
extern __shared__ __align__(1024) char dyn_smem[];

// ---------------- helpers --------------------------------------------------
__device__ __forceinline__ uint32_t smem_u32(const void* p) {
    return (uint32_t)__cvta_generic_to_shared(p);
}
__device__ __forceinline__ void cp16(uint32_t dst, const void* src) {
    asm volatile("cp.async.cg.shared.global [%0], [%1], 16;\n" ::"r"(dst), "l"(src));
}
__device__ __forceinline__ void cp16z(uint32_t dst, const void* src, int bytes) {
    asm volatile("cp.async.ca.shared.global [%0], [%1], 16, %2;\n" ::"r"(dst), "l"(src), "r"(bytes));
}
__device__ __forceinline__ void cp_commit() { asm volatile("cp.async.commit_group;\n"); }
template <int N> __device__ __forceinline__ void cp_wait() {
    asm volatile("cp.async.wait_group %0;\n" ::"n"(N));
}
__device__ __forceinline__ void mma_fp16(float c[4], const uint32_t a[4], uint32_t b0,
                                         uint32_t b1) {
    asm volatile(
        "mma.sync.aligned.m16n8k16.row.col.f32.f16.f16.f32 "
        "{%0,%1,%2,%3},{%4,%5,%6,%7},{%8,%9},{%0,%1,%2,%3};\n"
        : "+f"(c[0]), "+f"(c[1]), "+f"(c[2]), "+f"(c[3])
        : "r"(a[0]), "r"(a[1]), "r"(a[2]), "r"(a[3]), "r"(b0), "r"(b1));
}
__device__ __forceinline__ void ldsm4(uint32_t r[4], uint32_t addr) {
    asm volatile("ldmatrix.sync.aligned.m8n8.x4.shared.b16 {%0,%1,%2,%3}, [%4];"
                 : "=r"(r[0]), "=r"(r[1]), "=r"(r[2]), "=r"(r[3])
                 : "r"(addr));
}
__device__ __forceinline__ float sigmoidf_(float x) { return 1.0f / (1.0f + __expf(-x)); }

#define SMEM_SWZ128(x) ((x) ^ (((x) >> 3) & 0x70))

// ---------------- init / W convert ------------------------------------------
__global__ void zero_kernel() {
    int i = blockIdx.x * blockDim.x + threadIdx.x;
    if (i < BB * HH) {
        g_ha[i] = __float2half(0.f);
        g_c2[i] = 0.f;
    }
    if (i == 0) g_bar = 0u;
}

__global__ void wconv_kernel(const float* __restrict__ w) {
    size_t i = ((size_t)blockIdx.x * blockDim.x + threadIdx.x) * 4;
    if (i < (size_t)G4 * HH) {
        float4 v = *reinterpret_cast<const float4*>(w + i);
        g_w16[i] = __float2half(v.x);
        g_w16[i + 1] = __float2half(v.y);
        g_w16[i + 2] = __float2half(v.z);
        g_w16[i + 3] = __float2half(v.w);
    }
}

// ---------------- kernel 1: embedding gather + input projection (tf32 SIMT) -
#define LDA 36
#define XP_STAGE_FLOATS ((128 + 64) * LDA)
#define XP_SMEM_BYTES (2 * XP_STAGE_FLOATS * 4)

__device__ __forceinline__ void compute_block_tf32(const float* __restrict__ As,
                                                   const float* __restrict__ Bs,
                                                   float acc[2][4][4], int wm, int wn, int g,
                                                   int tig) {
#pragma unroll
    for (int k8 = 0; k8 < 32; k8 += 8) {
        uint32_t a[2][4];
#pragma unroll
        for (int mt = 0; mt < 2; mt++) {
            int r = wm + mt * 16;
            a[mt][0] = __float_as_uint(As[(r + g) * LDA + k8 + tig]);
            a[mt][1] = __float_as_uint(As[(r + g + 8) * LDA + k8 + tig]);
            a[mt][2] = __float_as_uint(As[(r + g) * LDA + k8 + tig + 4]);
            a[mt][3] = __float_as_uint(As[(r + g + 8) * LDA + k8 + tig + 4]);
        }
        uint32_t b[4][2];
#pragma unroll
        for (int nt = 0; nt < 4; nt++) {
            int cc = wn + nt * 8 + g;
            b[nt][0] = __float_as_uint(Bs[cc * LDA + k8 + tig]);
            b[nt][1] = __float_as_uint(Bs[cc * LDA + k8 + tig + 4]);
        }
#pragma unroll
        for (int mt = 0; mt < 2; mt++)
#pragma unroll
            for (int nt = 0; nt < 4; nt++) {
                float* c = acc[mt][nt];
                asm volatile(
                    "mma.sync.aligned.m16n8k8.row.col.f32.tf32.tf32.f32 "
                    "{%0,%1,%2,%3},{%4,%5,%6,%7},{%8,%9},{%0,%1,%2,%3};\n"
                    : "+f"(c[0]), "+f"(c[1]), "+f"(c[2]), "+f"(c[3])
                    : "r"(a[mt][0]), "r"(a[mt][1]), "r"(a[mt][2]), "r"(a[mt][3]), "r"(b[nt][0]),
                      "r"(b[nt][1]));
            }
    }
}

__global__ void __launch_bounds__(256) xproj_kernel(const int* __restrict__ input,
                                                    const float* __restrict__ embed,
                                                    const float* __restrict__ w_ih,
                                                    const float* __restrict__ b_ih,
                                                    const float* __restrict__ b_hh) {
    float* smem = reinterpret_cast<float*>(dyn_smem);
    __shared__ int tok[128];

    const int tid = threadIdx.x;
    const int t = blockIdx.x;
    const int n0 = blockIdx.y * 64;

    if (tid < 128) tok[tid] = input[tid * TT + t];
    __syncthreads();

    const int wid = tid >> 5, lane = tid & 31;
    const int wm = (wid & 3) * 32, wn = (wid >> 2) * 32;
    const int g = lane >> 2, tig = lane & 3;

    auto load_tiles = [&](int kb, int s) {
        float* As = smem + s * XP_STAGE_FLOATS;
        float* Bs = As + 128 * LDA;
        int k0 = kb * 32;
#pragma unroll
        for (int i = 0; i < 4; i++) {
            int lin = tid + i * 256;
            int row = lin >> 3;
            int kk4 = (lin & 7) * 4;
            int k = k0 + kk4;
            int rem = EE - k;
            int bytes = rem >= 4 ? 16 : (rem > 0 ? rem * 4 : 0);
            const float* src = embed + (size_t)tok[row] * EE + (bytes ? k : 0);
            cp16z(smem_u32(&As[row * LDA + kk4]), src, bytes);
        }
#pragma unroll
        for (int i = 0; i < 2; i++) {
            int lin = tid + i * 256;
            int col = lin >> 3;
            int kk4 = (lin & 7) * 4;
            int k = k0 + kk4;
            int rem = EE - k;
            int bytes = rem >= 4 ? 16 : (rem > 0 ? rem * 4 : 0);
            const float* src = w_ih + (size_t)(n0 + col) * EE + (bytes ? k : 0);
            cp16z(smem_u32(&Bs[col * LDA + kk4]), src, bytes);
        }
        cp_commit();
    };

    float acc[2][4][4] = {};
    const int NKB = (EE + 31) / 32;  // 10
    load_tiles(0, 0);
    for (int kb = 0; kb < NKB; kb++) {
        if (kb + 1 < NKB) {
            load_tiles(kb + 1, (kb + 1) & 1);
            cp_wait<1>();
        } else {
            cp_wait<0>();
        }
        __syncthreads();
        const float* As = smem + (kb & 1) * XP_STAGE_FLOATS;
        compute_block_tf32(As, As + 128 * LDA, acc, wm, wn, g, tig);
        __syncthreads();
    }

    // epilogue -> g_gx2[t][cb][row][gate*16+hc], + biases
#pragma unroll
    for (int mt = 0; mt < 2; mt++) {
#pragma unroll
        for (int nt = 0; nt < 4; nt++) {
            int row0 = wm + mt * 16 + g;
            int col0 = wn + nt * 8 + 2 * tig;
            int j0 = n0 + col0;
            int gate = j0 >> 11;
            int q = j0 & 2047;
            int cb = q >> 4;
            int hc = q & 15;
            float bias0 = b_ih[j0] + b_hh[j0];
            float bias1 = b_ih[j0 + 1] + b_hh[j0 + 1];
            size_t base0 = (((size_t)t * 128 + cb) * 128 + row0) * 64 + gate * 16 + hc;
            g_gx2[base0] = acc[mt][nt][0] + bias0;
            g_gx2[base0 + 1] = acc[mt][nt][1] + bias1;
            size_t base2 = base0 + 8 * 64;
            g_gx2[base2] = acc[mt][nt][2] + bias0;
            g_gx2[base2 + 1] = acc[mt][nt][3] + bias1;
        }
    }
}

// ---------------- kernel 2: persistent fp16 LSTM (all 64 steps) -------------
// 128 resident CTAs; CTA cb computes D[128 batch, 64 cols], col = gate*16+hc.
// KC=128 chunks (two 128B sub-tiles each); NSTG=3; gx prefetched into smem.
#define KC 128
#define NCHUNK (HH / KC)                       // 16
#define ASUB_BYTES (128 * 128)                 // A sub-tile 16 KB
#define BSUB_BYTES (64 * 128)                  // B sub-tile 8 KB
#define A_BYTES (2 * ASUB_BYTES)               // 32 KB per stage
#define STG_BYTES (A_BYTES + 2 * BSUB_BYTES)   // 49152
#define NSTG 3
#define GX_OFF (NSTG * STG_BYTES)              // 147456
#define STEP_SMEM_BYTES (GX_OFF + 128 * 64 * 4)  // 180224
#define STEP_THREADS 256

__global__ void __launch_bounds__(STEP_THREADS) step_persistent(float* __restrict__ d_out) {
    const uint32_t sbase = smem_u32(dyn_smem);
    const int tid = threadIdx.x;
    const int wid = tid >> 5, lane = tid & 31;
    const int cb = blockIdx.x;
    const int h0 = cb * 16;
    const int wm = (wid & 3) * 32, wn = (wid >> 2) * 32;

    // per-lane ldmatrix coordinates
    const int arow = lane & 15;                        // A: row within 16-row tile
    const int acs = lane >> 4;                         // A: k-chunk select (0/1)
    const int brow = (lane & 7) + ((lane & 16) >> 1);  // B: row within 16-row group
    const int bcs = (lane >> 3) & 1;                   // B: k-chunk select
    const int g8 = lane >> 2, tig = lane & 3;

    for (int t = 0; t < TT; t++) {
        const __half* __restrict__ h_in = (t & 1) ? g_hb : g_ha;
        __half* __restrict__ h_out = (t & 1) ? g_ha : g_hb;

        auto issue_stage = [&](int c, int s) {
            uint32_t base = sbase + s * STG_BYTES;
#pragma unroll
            for (int s2 = 0; s2 < 2; s2++) {
                int k0 = c * KC + s2 * 64;
                uint32_t abase = base + s2 * ASUB_BYTES;
                uint32_t bbase = base + A_BYTES + s2 * BSUB_BYTES;
#pragma unroll
                for (int i = 0; i < 4; i++) {
                    int lin = tid + i * STEP_THREADS;
                    int row = lin >> 3;
                    int o16 = lin & 7;
                    uint32_t sw = SMEM_SWZ128(row * 128 + o16 * 16);
                    cp16(abase + sw, &h_in[row * HH + k0 + o16 * 8]);
                }
#pragma unroll
                for (int i = 0; i < 2; i++) {
                    int lin = tid + i * STEP_THREADS;
                    int n = lin >> 3;
                    int o16 = lin & 7;
                    int j = (n >> 4) * HH + h0 + (n & 15);
                    uint32_t sw = SMEM_SWZ128(n * 128 + o16 * 16);
                    cp16(bbase + sw, &g_w16[(size_t)j * HH + k0 + o16 * 8]);
                }
            }
            cp_commit();
        };

        // gx prefetch (joins stage-0's group -> complete before chunk 0 compute)
        {
            const float* gx = &g_gx2[(((size_t)t * 128 + cb) * 128) * 64];
#pragma unroll
            for (int i = 0; i < 8; i++) {
                int lin = tid + i * STEP_THREADS;
                cp16(sbase + GX_OFF + lin * 16, gx + lin * 4);
            }
        }

        float acc[2][4][4] = {};

        issue_stage(0, 0);
        issue_stage(1, 1);

        for (int kb = 0; kb < NCHUNK; kb++) {
            cp_wait<1>();
            __syncthreads();
            int kn = kb + 2;
            if (kn < NCHUNK) issue_stage(kn, kn % NSTG);
            else cp_commit();  // keep group count exact in tail
            const uint32_t base = sbase + (kb % NSTG) * STG_BYTES;

            // register double-buffered fragments: load q+1 while mma q
            uint32_t a[2][2][4], b[2][2][4];
            auto load_frags = [&](int q, int pb) {
                const int ks = q >> 2, qq = q & 3;
                const uint32_t ab = base + ks * ASUB_BYTES;
                const uint32_t bb = base + A_BYTES + ks * BSUB_BYTES;
#pragma unroll
                for (int mt = 0; mt < 2; mt++) {
                    int row = wm + mt * 16 + arow;
                    uint32_t sw = SMEM_SWZ128(row * 128 + (2 * qq + acs) * 16);
                    ldsm4(a[pb][mt], ab + sw);
                }
#pragma unroll
                for (int nh = 0; nh < 2; nh++) {
                    int n = wn + nh * 16 + brow;
                    uint32_t sw = SMEM_SWZ128(n * 128 + (2 * qq + bcs) * 16);
                    ldsm4(b[pb][nh], bb + sw);
                }
            };
            load_frags(0, 0);
#pragma unroll
            for (int q = 0; q < 8; q++) {
                if (q < 7) load_frags(q + 1, (q + 1) & 1);
                const int pb = q & 1;
#pragma unroll
                for (int mt = 0; mt < 2; mt++)
#pragma unroll
                    for (int nt = 0; nt < 4; nt++)
                        mma_fp16(acc[mt][nt], a[pb][mt], b[pb][nt >> 1][(nt & 1) * 2],
                                 b[pb][nt >> 1][(nt & 1) * 2 + 1]);
            }
        }

        __syncthreads();

        // stage gates in smem: gsm[128][65] floats (33280 B, stages 0-1)
        float* gsm = reinterpret_cast<float*>(dyn_smem);
#pragma unroll
        for (int mt = 0; mt < 2; mt++) {
#pragma unroll
            for (int nt = 0; nt < 4; nt++) {
                int row0 = wm + mt * 16 + g8;
                int col0 = wn + nt * 8 + 2 * tig;
                gsm[row0 * 65 + col0] = acc[mt][nt][0];
                gsm[row0 * 65 + col0 + 1] = acc[mt][nt][1];
                gsm[(row0 + 8) * 65 + col0] = acc[mt][nt][2];
                gsm[(row0 + 8) * 65 + col0 + 1] = acc[mt][nt][3];
            }
        }
        __syncthreads();

        // LSTM cell: 128 b x 16 h, 8 per thread; gx read from smem
        {
            const float* __restrict__ gxs = reinterpret_cast<const float*>(dyn_smem + GX_OFF);
            const int b = tid >> 1;
            const int hh = (tid & 1) * 8;
            float* __restrict__ cc = &g_c2[(cb * 128 + b) * 16];
#pragma unroll
            for (int i = 0; i < 8; i++) {
                int hc = hh + i;
                float xi = gsm[b * 65 + 0 * 16 + hc] + gxs[b * 64 + 0 * 16 + hc];
                float xf = gsm[b * 65 + 1 * 16 + hc] + gxs[b * 64 + 1 * 16 + hc];
                float xg = gsm[b * 65 + 2 * 16 + hc] + gxs[b * 64 + 2 * 16 + hc];
                float xo = gsm[b * 65 + 3 * 16 + hc] + gxs[b * 64 + 3 * 16 + hc];
                float ig = sigmoidf_(xi);
                float fg = sigmoidf_(xf);
                float gg = tanhf(xg);
                float og = sigmoidf_(xo);
                float cn = fg * cc[hc] + ig * gg;
                cc[hc] = cn;
                float hv = og * tanhf(cn);
                h_out[b * HH + h0 + hc] = __float2half(hv);
                if (t == TT - 1) d_out[b * HH + h0 + hc] = hv;
            }
        }

        // ---- global barrier (all 128 CTAs) ----
        if (t < TT - 1) {
            __syncthreads();
            __threadfence();
            if (tid == 0) {
                atomicAdd(&g_bar, 1u);
                const unsigned target = 128u * (unsigned)(t + 1);
                unsigned v;
                do {
                    asm volatile("ld.acquire.gpu.global.u32 %0, [%1];" : "=r"(v) : "l"(&g_bar));
                    if (v < target) __nanosleep(64);
                } while (v < target);
            }
            __syncthreads();
        }
    }
}

// ---------------- launch ----------------------------------------------------
extern "C" void kernel_launch(void* const* d_in, const int* in_sizes, int n_in, void* d_out,
                              int out_size) {
    const int* input = (const int*)d_in[0];
    const float* embed = (const float*)d_in[1];
    const float* w_ih = (const float*)d_in[2];
    const float* w_hh = (const float*)d_in[3];
    const float* b_ih = (const float*)d_in[4];
    const float* b_hh = (const float*)d_in[5];
    float* out = (float*)d_out;

    cudaFuncSetAttribute(xproj_kernel, cudaFuncAttributeMaxDynamicSharedMemorySize, XP_SMEM_BYTES);
    cudaFuncSetAttribute(step_persistent, cudaFuncAttributeMaxDynamicSharedMemorySize,
                         STEP_SMEM_BYTES);

    zero_kernel<<<(BB * HH + 255) / 256, 256>>>();
    wconv_kernel<<<(int)(((size_t)G4 * HH / 4 + 255) / 256), 256>>>(w_hh);
    xproj_kernel<<<dim3(TT, 128), 256, XP_SMEM_BYTES>>>(input, embed, w_ih, b_ih, b_hh);
    step_persistent<<<128, STEP_THREADS, STEP_SMEM_BYTES>>>(out);
}